// round 13
// baseline (speedup 1.0000x reference)
#include <cuda_runtime.h>
#include <cuda_bf16.h>
#include <math.h>
#include <stdint.h>

#define CDIM 256
#define NDIM 4096
#define BDIM 8
#define QR   128
#define TK   64
#define NT   (NDIM / TK)   // 64

__device__ __nv_bfloat16 g_q[(size_t)BDIM * NDIM * CDIM];   // [b][n][c]
__device__ __nv_bfloat16 g_k[(size_t)BDIM * NDIM * CDIM];   // [b][n][c]
__device__ __nv_bfloat16 g_v[(size_t)BDIM * NDIM * CDIM];   // [b][c][n] (transposed)
__device__ __nv_bfloat16 g_xh[(size_t)BDIM * NDIM * CDIM];  // x^T hi [b][n][c]
__device__ __nv_bfloat16 g_xl[(size_t)BDIM * NDIM * CDIM];  // x^T lo
__device__ __nv_bfloat16 g_wh[4 * CDIM * CDIM];             // W hi [p][o][c]
__device__ __nv_bfloat16 g_wl[4 * CDIM * CDIM];             // W lo

// ---- attn smem byte offsets (tile swizzle: 16B chunk ^= row&7) ----
#define SQ_OFF 0u          // 128 x 256 bf16 = 64KB
#define SK_OFF 65536u      // 2 x (64 x 256 bf16) = 64KB
#define SV_OFF 131072u     // 2 x (256 x 64 bf16) = 64KB
#define SP_OFF 196608u     // 128 x 64 bf16 (row 128B) = 16KB
#define SL_OFF 212992u     // 2 x 128 f32 = 1KB
#define SM_BYTES 214016u

// ---- proj2 smem byte offsets (per buffer; 2 buffers) ----
#define P2_XH 0u           // 128n x 64c bf16 (row 128B, 8 chunks)
#define P2_XL 16384u       // only loaded for p=3
#define P2_WH 32768u       // 256o x 64c bf16
#define P2_WL 65536u       // only loaded for p=3
#define P2_BUF 98304u
#define P2_BYTES 196608u

// ---------------- helpers ----------------
__device__ __forceinline__ uint32_t smem_u32(const void* p) {
    uint32_t a;
    asm("{ .reg .u64 t; cvta.to.shared.u64 t, %1; cvt.u32.u64 %0, t; }" : "=r"(a) : "l"(p));
    return a;
}
__device__ __forceinline__ float ex2(float x) {
    float y; asm("ex2.approx.f32 %0, %1;" : "=f"(y) : "f"(x)); return y;
}
__device__ __forceinline__ uint32_t bf2(float lo, float hi) {
    __nv_bfloat162 h = __float22bfloat162_rn(make_float2(lo, hi));
    return *(uint32_t*)&h;
}
__device__ __forceinline__ void cp16(uint32_t saddr, const void* gaddr) {
    asm volatile("cp.async.cg.shared.global [%0], [%1], 16;" :: "r"(saddr), "l"(gaddr));
}
__device__ __forceinline__ void cp_commit() {
    asm volatile("cp.async.commit_group;" ::: "memory");
}
template <int N>
__device__ __forceinline__ void cp_wait() {
    asm volatile("cp.async.wait_group %0;" :: "n"(N) : "memory");
}
__device__ __forceinline__ void ldm4(uint32_t* r, uint32_t addr) {
    asm volatile("ldmatrix.sync.aligned.m8n8.x4.shared.b16 {%0,%1,%2,%3}, [%4];"
        : "=r"(r[0]), "=r"(r[1]), "=r"(r[2]), "=r"(r[3]) : "r"(addr));
}
__device__ __forceinline__ void mma16(float* d, const uint32_t* a, uint32_t b0, uint32_t b1) {
    asm volatile("mma.sync.aligned.m16n8k16.row.col.f32.bf16.bf16.f32 "
        "{%0,%1,%2,%3}, {%4,%5,%6,%7}, {%8,%9}, {%0,%1,%2,%3};"
        : "+f"(d[0]), "+f"(d[1]), "+f"(d[2]), "+f"(d[3])
        : "r"(a[0]), "r"(a[1]), "r"(a[2]), "r"(a[3]), "r"(b0), "r"(b1));
}

// ---------------- x transpose + hi/lo bf16 split (unchanged) ---------------
__global__ __launch_bounds__(256) void xpose_kernel(const float* __restrict__ x)
{
    __shared__ float sm[64 * 65];
    const int n0 = blockIdx.x * 64;
    const int c0 = blockIdx.y * 64;
    const int b  = blockIdx.z;
    const int tid = threadIdx.x;

    const float* xb = x + ((size_t)b * CDIM + c0) * NDIM + n0;
    #pragma unroll
    for (int j = 0; j < 4; j++) {
        int idx = tid + 256 * j;
        int cc = idx >> 4, nn4 = idx & 15;
        float4 v = *(const float4*)(xb + (size_t)cc * NDIM + nn4 * 4);
        float* s = sm + cc * 65 + nn4 * 4;
        s[0] = v.x; s[1] = v.y; s[2] = v.z; s[3] = v.w;
    }
    __syncthreads();
    __nv_bfloat16* dh = g_xh + ((size_t)b * NDIM + n0) * CDIM + c0;
    __nv_bfloat16* dl = g_xl + ((size_t)b * NDIM + n0) * CDIM + c0;
    #pragma unroll
    for (int j = 0; j < 8; j++) {
        int idx = tid + 256 * j;
        int nn = idx >> 5, cp = idx & 31;
        float f0 = sm[(2 * cp)     * 65 + nn];
        float f1 = sm[(2 * cp + 1) * 65 + nn];
        float h0 = __bfloat162float(__float2bfloat16(f0));
        float h1 = __bfloat162float(__float2bfloat16(f1));
        *(uint32_t*)(dh + (size_t)nn * CDIM + 2 * cp) = bf2(f0, f1);
        *(uint32_t*)(dl + (size_t)nn * CDIM + 2 * cp) = bf2(f0 - h0, f1 - h1);
    }
}

// ---------------- W hi/lo convert (unchanged) ----------------
__global__ __launch_bounds__(256) void wconv_kernel(
    const float* __restrict__ Wq, const float* __restrict__ Wk,
    const float* __restrict__ Wv, const float* __restrict__ Wp)
{
    const int p = blockIdx.x;
    const float* W = (p == 0) ? Wq : (p == 1) ? Wk : (p == 2) ? Wv : Wp;
    int idx4 = blockIdx.y * 256 + threadIdx.x;
    float4 v = *(const float4*)(W + idx4 * 4);
    float hx = __bfloat162float(__float2bfloat16(v.x));
    float hy = __bfloat162float(__float2bfloat16(v.y));
    float hz = __bfloat162float(__float2bfloat16(v.z));
    float hw = __bfloat162float(__float2bfloat16(v.w));
    uint2 uh = make_uint2(bf2(v.x, v.y), bf2(v.z, v.w));
    uint2 ul = make_uint2(bf2(v.x - hx, v.y - hy), bf2(v.z - hz, v.w - hw));
    *(uint2*)(g_wh + (size_t)p * CDIM * CDIM + idx4 * 4) = uh;
    *(uint2*)(g_wl + (size_t)p * CDIM * CDIM + idx4 * 4) = ul;
}

// ---------------- proj2: bf16 mma projections (unchanged from R12) ---------
__global__ __launch_bounds__(256, 1) void proj2_kernel(
    const float* __restrict__ bq, const float* __restrict__ bk,
    const float* __restrict__ bv, const float* __restrict__ bp,
    float* __restrict__ out)
{
    extern __shared__ char smc[];
    const uint32_t sm0 = smem_u32(smc);
    const int n0 = blockIdx.x * 128;
    const int p  = blockIdx.y;
    const int b  = blockIdx.z;
    const float* bias = (p == 0) ? bq : (p == 1) ? bk : (p == 2) ? bv : bp;
    const bool qk = (p < 2);
    const bool res = (p == 3);

    const int tid = threadIdx.x, lane = tid & 31, w = tid >> 5;
    const int g = lane >> 2, t = lane & 3;
    const int wm  = qk ? (w & 1) : (w >> 1);
    const int wn4 = qk ? (w >> 1) : (w & 1);

    const __nv_bfloat16* xh = g_xh + ((size_t)b * NDIM + n0) * CDIM;
    const __nv_bfloat16* xl = g_xl + ((size_t)b * NDIM + n0) * CDIM;
    const __nv_bfloat16* wh = g_wh + (size_t)p * CDIM * CDIM;
    const __nv_bfloat16* wl = g_wl + (size_t)p * CDIM * CDIM;

    auto load_chunk = [&](int kc, int buf) {
        const uint32_t base = sm0 + (uint32_t)buf * P2_BUF;
        #pragma unroll
        for (int j = 0; j < 4; j++) {
            int idx = tid + 256 * j, r = idx >> 3, ch = idx & 7;
            uint32_t so = (uint32_t)r * 128u + (uint32_t)((ch ^ (r & 7)) << 4);
            cp16(base + P2_XH + so, xh + (size_t)r * CDIM + kc * 64 + ch * 8);
        }
        #pragma unroll
        for (int j = 0; j < 8; j++) {
            int idx = tid + 256 * j, r = idx >> 3, ch = idx & 7;
            uint32_t so = (uint32_t)r * 128u + (uint32_t)((ch ^ (r & 7)) << 4);
            cp16(base + P2_WH + so, wh + (size_t)r * CDIM + kc * 64 + ch * 8);
        }
        if (res) {
            #pragma unroll
            for (int j = 0; j < 4; j++) {
                int idx = tid + 256 * j, r = idx >> 3, ch = idx & 7;
                uint32_t so = (uint32_t)r * 128u + (uint32_t)((ch ^ (r & 7)) << 4);
                cp16(base + P2_XL + so, xl + (size_t)r * CDIM + kc * 64 + ch * 8);
            }
            #pragma unroll
            for (int j = 0; j < 8; j++) {
                int idx = tid + 256 * j, r = idx >> 3, ch = idx & 7;
                uint32_t so = (uint32_t)r * 128u + (uint32_t)((ch ^ (r & 7)) << 4);
                cp16(base + P2_WL + so, wl + (size_t)r * CDIM + kc * 64 + ch * 8);
            }
        }
    };

    load_chunk(0, 0);
    cp_commit();

    const int rA  = ((lane >> 3) & 1) * 8 + (lane & 7);
    const int cAo = lane >> 4;
    const int rB_ = ((lane >> 4) & 1) * 8 + (lane & 7);
    const int cBo = (lane >> 3) & 1;
    const int xs  = lane & 7;

    float acc[4][8][4];
    #pragma unroll
    for (int mf = 0; mf < 4; mf++)
        #pragma unroll
        for (int nf = 0; nf < 8; nf++)
            #pragma unroll
            for (int k = 0; k < 4; k++) acc[mf][nf][k] = 0.f;

    for (int kc = 0; kc < 4; kc++) {
        const int buf = kc & 1;
        cp_wait<0>();
        __syncthreads();
        if (kc + 1 < 4) { load_chunk(kc + 1, buf ^ 1); cp_commit(); }

        const uint32_t base = sm0 + (uint32_t)buf * P2_BUF;
        const uint32_t offA1 = qk ? P2_XH : P2_WH;
        const uint32_t offB1 = qk ? P2_WH : P2_XH;
        const uint32_t aBase = base + (uint32_t)(64 * wm) * 128u + (uint32_t)rA * 128u;
        const uint32_t bBase = base + (uint32_t)(64 * wn4) * 128u + (uint32_t)rB_ * 128u;

        #pragma unroll
        for (int ks = 0; ks < 4; ks++) {
            const uint32_t ao = (uint32_t)(((2 * ks + cAo) ^ xs) << 4);
            const uint32_t bo = (uint32_t)(((2 * ks + cBo) ^ xs) << 4);
            uint32_t b1[4][4];
            #pragma unroll
            for (int nf2 = 0; nf2 < 4; nf2++)
                ldm4(b1[nf2], bBase + offB1 + (uint32_t)nf2 * 2048u + bo);
            if (!res) {
                #pragma unroll
                for (int mf = 0; mf < 4; mf++) {
                    uint32_t ah[4];
                    ldm4(ah, aBase + offA1 + (uint32_t)mf * 2048u + ao);
                    #pragma unroll
                    for (int nf2 = 0; nf2 < 4; nf2++) {
                        mma16(acc[mf][2 * nf2],     ah, b1[nf2][0], b1[nf2][1]);
                        mma16(acc[mf][2 * nf2 + 1], ah, b1[nf2][2], b1[nf2][3]);
                    }
                }
            } else {
                uint32_t b2[4][4];
                #pragma unroll
                for (int nf2 = 0; nf2 < 4; nf2++)
                    ldm4(b2[nf2], bBase + P2_XL + (uint32_t)nf2 * 2048u + bo);
                #pragma unroll
                for (int mf = 0; mf < 4; mf++) {
                    uint32_t ah[4], al[4];
                    ldm4(ah, aBase + P2_WH + (uint32_t)mf * 2048u + ao);
                    ldm4(al, aBase + P2_WL + (uint32_t)mf * 2048u + ao);
                    #pragma unroll
                    for (int nf2 = 0; nf2 < 4; nf2++) {
                        mma16(acc[mf][2 * nf2],     ah, b1[nf2][0], b1[nf2][1]);
                        mma16(acc[mf][2 * nf2 + 1], ah, b1[nf2][2], b1[nf2][3]);
                        mma16(acc[mf][2 * nf2],     ah, b2[nf2][0], b2[nf2][1]);
                        mma16(acc[mf][2 * nf2 + 1], ah, b2[nf2][2], b2[nf2][3]);
                        mma16(acc[mf][2 * nf2],     al, b1[nf2][0], b1[nf2][1]);
                        mma16(acc[mf][2 * nf2 + 1], al, b1[nf2][2], b1[nf2][3]);
                    }
                }
            }
        }
        __syncthreads();
    }

    if (qk) {
        __nv_bfloat16* dst = ((p == 0) ? g_q : g_k) + (size_t)b * NDIM * CDIM;
        #pragma unroll
        for (int mf = 0; mf < 4; mf++) {
            int n = n0 + 64 * wm + 16 * mf + g;
            #pragma unroll
            for (int nf = 0; nf < 8; nf++) {
                int o = 64 * wn4 + 8 * nf + 2 * t;
                float2 bs = *(const float2*)(bias + o);
                *(uint32_t*)(dst + (size_t)n * CDIM + o) =
                    bf2(acc[mf][nf][0] + bs.x, acc[mf][nf][1] + bs.y);
                *(uint32_t*)(dst + (size_t)(n + 8) * CDIM + o) =
                    bf2(acc[mf][nf][2] + bs.x, acc[mf][nf][3] + bs.y);
            }
        }
    } else if (p == 2) {
        __nv_bfloat16* dst = g_v + (size_t)b * CDIM * NDIM;
        #pragma unroll
        for (int mf = 0; mf < 4; mf++) {
            int o = 64 * wm + 16 * mf + g;
            float b0 = bias[o], b8 = bias[o + 8];
            #pragma unroll
            for (int nf = 0; nf < 8; nf++) {
                int n = n0 + 64 * wn4 + 8 * nf + 2 * t;
                *(uint32_t*)(dst + (size_t)o * NDIM + n) =
                    bf2(acc[mf][nf][0] + b0, acc[mf][nf][1] + b0);
                *(uint32_t*)(dst + (size_t)(o + 8) * NDIM + n) =
                    bf2(acc[mf][nf][2] + b8, acc[mf][nf][3] + b8);
            }
        }
    } else {
        float* dst = out + (size_t)b * CDIM * NDIM;
        #pragma unroll
        for (int mf = 0; mf < 4; mf++) {
            int o = 64 * wm + 16 * mf + g;
            float b0 = bias[o], b8 = bias[o + 8];
            #pragma unroll
            for (int nf = 0; nf < 8; nf++) {
                int n = n0 + 64 * wn4 + 8 * nf + 2 * t;
                *(float2*)(dst + (size_t)o * NDIM + n) =
                    make_float2(acc[mf][nf][0] + b0, acc[mf][nf][1] + b0);
                *(float2*)(dst + (size_t)(o + 8) * NDIM + n) =
                    make_float2(acc[mf][nf][2] + b8, acc[mf][nf][3] + b8);
            }
        }
    }
}

// ---------------- K/V tile loader (cp.async, bf16, swizzled) ---------------
__device__ __forceinline__ void load_kv(uint32_t sm0, const __nv_bfloat16* kb,
                                        const __nv_bfloat16* vb, int i, int buf, int tid)
{
    const int m0 = i * TK;
    const uint32_t sk = sm0 + SK_OFF + (uint32_t)buf * 32768u;
    const uint32_t sv = sm0 + SV_OFF + (uint32_t)buf * 32768u;
    #pragma unroll
    for (int j = 0; j < 8; j++) {          // K: 64 keys x 256 c
        int idx = tid + 256 * j, r = idx >> 5, ch = idx & 31;
        cp16(sk + (uint32_t)r * 512u + (uint32_t)((ch ^ (r & 7)) << 4),
             kb + (size_t)(m0 + r) * CDIM + ch * 8);
    }
    #pragma unroll
    for (int j = 0; j < 8; j++) {          // V^T: 256 c x 64 keys
        int idx = tid + 256 * j, r = idx >> 3, ch = idx & 7;
        cp16(sv + (uint32_t)r * 128u + (uint32_t)((ch ^ (r & 7)) << 4),
             vb + (size_t)r * NDIM + m0 + ch * 8);
    }
}

// ---------------- bf16 mma flash attention: pair-split, named barriers -----
// grid (32, 8), 256 thr, 8 warps: pair wm=w>>1 owns rows [32wm,32wm+32);
// half wn=w&1. S warp tile 32x32 (wn = key half) -> P smem (shared in pair via
// bar.sync 1+wm,64); PV warp tile 32x128 (wn = channel half) over all 64 keys.
// One CTA sync + one 2-warp barrier per tile.
__global__ __launch_bounds__(256, 1) void attn_kernel(float* __restrict__ out)
{
    extern __shared__ char smc[];
    const uint32_t sm0 = smem_u32(smc);
    const int tid = threadIdx.x, lane = tid & 31;
    const int w = tid >> 5, wm = w >> 1, wn = w & 1;
    const int g = lane >> 2, t = lane & 3;
    const int b = blockIdx.y, n0 = blockIdx.x * QR;

    const __nv_bfloat16* qb = g_q + ((size_t)b * NDIM + n0) * CDIM;
    const __nv_bfloat16* kb = g_k + (size_t)b * NDIM * CDIM;
    const __nv_bfloat16* vb = g_v + (size_t)b * CDIM * NDIM;

    // prologue: Q (128x256) + tile0 in one cp.async group
    #pragma unroll
    for (int j = 0; j < 16; j++) {
        int idx = tid + 256 * j, r = idx >> 5, ch = idx & 31;
        cp16(sm0 + SQ_OFF + (uint32_t)r * 512u + (uint32_t)((ch ^ (r & 7)) << 4),
             qb + (size_t)r * CDIM + ch * 8);
    }
    load_kv(sm0, kb, vb, 0, 0, tid);
    cp_commit();

    // ldmatrix lane geometry
    const int rA  = ((lane >> 3) & 1) * 8 + (lane & 7);   // A row-in-16
    const int cAo = lane >> 4;
    const int rB_ = ((lane >> 4) & 1) * 8 + (lane & 7);   // B row-in-16
    const int cBo = (lane >> 3) & 1;
    const int xs  = lane & 7;                             // swizzle XOR
    const uint32_t qA0 = sm0 + SQ_OFF + (uint32_t)(32 * wm + rA) * 512u;
    const uint32_t qA1 = qA0 + 8192u;                     // +16 rows
    const uint32_t pA0 = sm0 + SP_OFF + (uint32_t)(32 * wm + rA) * 128u;
    const uint32_t pA1 = pA0 + 2048u;                     // +16 rows

    float hacc[2][16][4];
    #pragma unroll
    for (int mf = 0; mf < 2; mf++)
        #pragma unroll
        for (int nf = 0; nf < 16; nf++)
            #pragma unroll
            for (int k = 0; k < 4; k++) hacc[mf][nf][k] = 0.f;
    float lsum[2][2] = {{0.f, 0.f}, {0.f, 0.f}};
    const float EC = 0.0901684400555602f;    // log2(e)/16

    for (int i = 0; i < NT; i++) {
        const int buf = i & 1;
        cp_wait<0>();                         // tile i resident
        __syncthreads();                      // buf^1 + P reads of tile i-1 done
        if (i + 1 < NT) { load_kv(sm0, kb, vb, i + 1, buf ^ 1, tid); cp_commit(); }

        // ---- S = Q K^T (warp tile 32 rows x 32 keys; wn = key half) ----
        float sacc[2][4][4];
        #pragma unroll
        for (int mf = 0; mf < 2; mf++)
            #pragma unroll
            for (int f = 0; f < 4; f++)
                #pragma unroll
                for (int k = 0; k < 4; k++) sacc[mf][f][k] = 0.f;
        const uint32_t kB0 = sm0 + SK_OFF + (uint32_t)buf * 32768u
                           + (uint32_t)(32 * wn + rB_) * 512u;
        const uint32_t kB1 = kB0 + 8192u;    // +16 key rows
        #pragma unroll
        for (int ks = 0; ks < 16; ks++) {
            uint32_t aq0[4], aq1[4], b0[4], b1[4];
            uint32_t ao = (uint32_t)(((2 * ks + cAo) ^ xs) << 4);
            ldm4(aq0, qA0 + ao);
            ldm4(aq1, qA1 + ao);
            uint32_t ko = (uint32_t)(((2 * ks + cBo) ^ xs) << 4);
            ldm4(b0, kB0 + ko);
            ldm4(b1, kB1 + ko);
            mma16(sacc[0][0], aq0, b0[0], b0[1]);
            mma16(sacc[0][1], aq0, b0[2], b0[3]);
            mma16(sacc[0][2], aq0, b1[0], b1[1]);
            mma16(sacc[0][3], aq0, b1[2], b1[3]);
            mma16(sacc[1][0], aq1, b0[0], b0[1]);
            mma16(sacc[1][1], aq1, b0[2], b0[3]);
            mma16(sacc[1][2], aq1, b1[0], b1[1]);
            mme_dummy: ;
            mma16(sacc[1][3], aq1, b1[2], b1[3]);
        }

        // ---- softmax (max-free) -> sP bf16, accumulate l ----
        #pragma unroll
        for (int mf = 0; mf < 2; mf++) {
            char* p0p = smc + SP_OFF + (32 * wm + 16 * mf + g) * 128 + 4 * t;
            char* p1p = p0p + 8 * 128;
            #pragma unroll
            for (int f = 0; f < 4; f++) {
                float e0 = ex2(sacc[mf][f][0] * EC);
                float e1 = ex2(sacc[mf][f][1] * EC);
                float e2 = ex2(sacc[mf][f][2] * EC);
                float e3 = ex2(sacc[mf][f][3] * EC);
                lsum[mf][0] += e0 + e1;
                lsum[mf][1] += e2 + e3;
                int off = ((4 * wn + f) ^ g) << 4;
                *(uint32_t*)(p0p + off) = bf2(e0, e1);
                *(uint32_t*)(p1p + off) = bf2(e2, e3);
            }
        }
        // pair barrier: partner's P half visible (2 warps, ids 1..4)
        asm volatile("bar.sync %0, %1;" :: "r"(1 + wm), "r"(64) : "memory");

        // ---- H += P V (warp tile 32 x 128; wn = channel half) ----
        const uint32_t vB = sm0 + SV_OFF + (uint32_t)buf * 32768u
                          + (uint32_t)(128 * wn + rB_) * 128u;
        #pragma unroll
        for (int ks = 0; ks < 4; ks++) {
            uint32_t ap0[4], ap1[4];
            uint32_t po = (uint32_t)(((2 * ks + cAo) ^ xs) << 4);
            ldm4(ap0, pA0 + po);
            ldm4(ap1, pA1 + po);
            uint32_t vo = (uint32_t)(((2 * ks + cBo) ^ xs) << 4);
            #pragma unroll
            for (int nb = 0; nb < 8; nb++) {
                uint32_t bv[4];
                ldm4(bv, vB + (uint32_t)nb * 2048u + vo);
                mma16(hacc[0][2 * nb],     ap0, bv[0], bv[1]);
                mma16(hacc[0][2 * nb + 1], ap0, bv[2], bv[3]);
                mma16(hacc[1][2 * nb],     ap1, bv[0], bv[1]);
                mma16(hacc[1][2 * nb + 1], ap1, bv[2], bv[3]);
            }
        }
    }

    // ---- l reduction (t lanes, then wn halves via smem) ----
    float* sl = (float*)(smc + SL_OFF);
    #pragma unroll
    for (int mf = 0; mf < 2; mf++) {
        #pragma unroll
        for (int h = 0; h < 2; h++) {
            lsum[mf][h] += __shfl_xor_sync(0xffffffffu, lsum[mf][h], 1);
            lsum[mf][h] += __shfl_xor_sync(0xffffffffu, lsum[mf][h], 2);
        }
        if (t == 0) {
            sl[wn * QR + 32 * wm + 16 * mf + g]     = lsum[mf][0];
            sl[wn * QR + 32 * wm + 16 * mf + 8 + g] = lsum[mf][1];
        }
    }
    __syncthreads();

    // ---- epilogue: out[b][c][n] += h / l ----
    float* ob = out + (size_t)b * CDIM * NDIM + n0;
    #pragma unroll
    for (int mf = 0; mf < 2; mf++) {
        const int r0 = 32 * wm + 16 * mf + g;
        float li0 = 1.f / (sl[r0]     + sl[QR + r0]);
        float li1 = 1.f / (sl[r0 + 8] + sl[QR + r0 + 8]);
        #pragma unroll
        for (int nf = 0; nf < 16; nf++) {
            int c = 128 * wn + 8 * nf + 2 * t;
            float* d0 = ob + (size_t)c * NDIM + r0;
            float* d1 = d0 + NDIM;
            d0[0] += hacc[mf][nf][0] * li0;
            d1[0] += hacc[mf][nf][1] * li0;
            d0[8] += hacc[mf][nf][2] * li1;
            d1[8] += hacc[mf][nf][3] * li1;
        }
    }
}

extern "C" void kernel_launch(void* const* d_in, const int* in_sizes, int n_in,
                              void* d_out, int out_size)
{
    const float* x  = (const float*)d_in[0];
    const float* Wq = (const float*)d_in[1];
    const float* bq = (const float*)d_in[2];
    const float* Wk = (const float*)d_in[3];
    const float* bk = (const float*)d_in[4];
    const float* Wv = (const float*)d_in[5];
    const float* bv = (const float*)d_in[6];
    const float* Wp = (const float*)d_in[7];
    const float* bp = (const float*)d_in[8];
    float* out = (float*)d_out;

    cudaFuncSetAttribute(proj2_kernel,
                         cudaFuncAttributeMaxDynamicSharedMemorySize, P2_BYTES);
    cudaFuncSetAttribute(attn_kernel,
                         cudaFuncAttributeMaxDynamicSharedMemorySize, SM_BYTES);

    xpose_kernel<<<dim3(64, 4, 8), 256>>>(x);
    wconv_kernel<<<dim3(4, 64), 256>>>(Wq, Wk, Wv, Wp);
    proj2_kernel<<<dim3(32, 4, 8), 256, P2_BYTES>>>(bq, bk, bv, bp, out);
    attn_kernel<<<dim3(NDIM / QR, BDIM), 256, SM_BYTES>>>(out);
}